// round 13
// baseline (speedup 1.0000x reference)
#include <cuda_runtime.h>
#include <cstdint>

// CategorySpecificLinear via mma.sync.m16n8k8 TF32 (base sm_103; tcgen05 is
// rejected by this bench's ptxas target).
//
// Round 13: r10 structure (CTA 256Mx128N, 256 thr, 8 warps 4Mx2N, warp 64x64,
// 4-stage cp.async, x4-unrolled loop, mid-chunk barrier+ISSUE, cross-chunk
// preload) with fb SINGLE-buffered JIT. Register budget finally fits:
// 128 acc + 32 fa + 16 fb + ~30 misc ~= 206 < 255 -> no spills.

#define A_STAGE  32768                 // 256 x 32 f32, 128B rows, XOR swizzle
#define B_STAGE  17408                 // 32 x 136 f32
#define B_REG    (4 * A_STAGE)         // 131072
#define SMEM_DYN (4 * A_STAGE + 4 * B_STAGE)   // 200704

static __device__ __forceinline__ uint32_t smem_u32(const void* p){
    uint32_t a;
    asm("{ .reg .u64 t; cvta.to.shared.u64 t, %1; cvt.u32.u64 %0, t; }" : "=r"(a) : "l"(p));
    return a;
}
static __device__ __forceinline__ void cp16(uint32_t dst, const void* src){
    asm volatile("cp.async.cg.shared.global [%0], [%1], 16;"
                 :: "r"(dst), "l"(src) : "memory");
}
static __device__ __forceinline__ uint32_t f2tf(uint32_t bits){
    uint32_t r;
    asm("cvt.rna.tf32.f32 %0, %1;" : "=r"(r) : "f"(__uint_as_float(bits)));
    return r;
}
static __device__ __forceinline__ void mma_tf32(float d[4],
                                                uint32_t a0, uint32_t a1,
                                                uint32_t a2, uint32_t a3,
                                                uint32_t b0, uint32_t b1){
    asm volatile(
        "mma.sync.aligned.m16n8k8.row.col.f32.tf32.tf32.f32 "
        "{%0,%1,%2,%3}, {%4,%5,%6,%7}, {%8,%9}, {%0,%1,%2,%3};"
        : "+f"(d[0]), "+f"(d[1]), "+f"(d[2]), "+f"(d[3])
        : "r"(a0), "r"(a1), "r"(a2), "r"(a3), "r"(b0), "r"(b1));
}
static __device__ __forceinline__ uint32_t lds32(const char* p){
    return *(const uint32_t*)p;
}

__global__ __launch_bounds__(256, 1)
void cslin_mma11_kernel(const float* __restrict__ x,
                        const int*   __restrict__ cat_ids,
                        const float* __restrict__ W,
                        const float* __restrict__ bias,
                        float*       __restrict__ y)
{
    constexpr int IDIM = 1024, ODIM = 1024, TDIM = 512;
    extern __shared__ char dsm[];

    const int tid  = threadIdx.x;
    const int wid  = tid >> 5;
    const int lane = tid & 31;
    const int la3  = lane & 3;
    const int lg   = lane >> 2;

    const int n0 = blockIdx.x * 128;
    const int m0 = blockIdx.y * 256;
    const int bb = blockIdx.z;
    const int cat = __ldg(cat_ids + bb);

    const float* xb = x + (size_t)bb  * TDIM * IDIM;
    const float* Wc = W + (size_t)cat * IDIM * ODIM;
    const float* bc = bias + (size_t)cat * ODIM;
    float*       yb = y + (size_t)bb  * TDIM * ODIM;

    // ---- cp.async geometry ----
    const float* aSrc = xb + (size_t)(m0 + (tid >> 3)) * IDIM + ((tid & 7) << 2);
    const uint32_t aDst = smem_u32(dsm)
        + (uint32_t)((tid >> 3) * 128)
        + (uint32_t)((((tid & 7) << 4)) ^ ((((tid >> 3) & 7)) << 4));
    const float* bSrc = Wc + (size_t)(tid >> 5) * ODIM + n0 + ((tid & 31) << 2);
    const uint32_t bDst = smem_u32(dsm) + B_REG
        + (uint32_t)((tid >> 5) * 544 + ((tid & 31) << 4));

#define ISSUE(KC, S)                                                          \
    do {                                                                      \
        const float* _as = aSrc + (KC);                                       \
        const uint32_t _ad = aDst + (uint32_t)((S) * A_STAGE);                \
        _Pragma("unroll")                                                     \
        for (int i = 0; i < 8; i++)                                           \
            cp16(_ad + (uint32_t)(i * 4096), _as + (size_t)(32 * i) * IDIM);  \
        const float* _bs = bSrc + (size_t)(KC) * ODIM;                        \
        const uint32_t _bd = bDst + (uint32_t)((S) * B_STAGE);                \
        _Pragma("unroll")                                                     \
        for (int i = 0; i < 4; i++)                                           \
            cp16(_bd + (uint32_t)(i * 4352), _bs + (size_t)(8 * i) * ODIM);   \
    } while (0)

    // ---- warp tile 64x64 invariants ----
    const int wm = (wid & 3) * 64;
    const int wn = (wid >> 2) * 64;

    const uint32_t swzA = (uint32_t)(lg << 4);
    const uint32_t aInv = (uint32_t)((wm + lg) * 128);
    const uint32_t bInv = (uint32_t)(la3 * 544 + (wn + lg) * 4);
    const uint32_t aK   = (uint32_t)(la3 * 4);

    float acc[4][8][4];
    #pragma unroll
    for (int i = 0; i < 4; i++)
        #pragma unroll
        for (int j = 0; j < 8; j++)
            #pragma unroll
            for (int q = 0; q < 4; q++) acc[i][j][q] = 0.f;

    uint32_t fa0[16], fa1[16], fb[16];

#define LOAD_FA(FA, SA, KS)                                                   \
    do {                                                                      \
        const uint32_t _c0 = ((uint32_t)((KS) * 32) + aK) ^ swzA;             \
        const char* _pa0 = (SA) + (aInv + _c0);                               \
        const char* _pa1 = (SA) + (aInv + (_c0 ^ 16u));                       \
        _Pragma("unroll")                                                     \
        for (int i = 0; i < 4; i++){                                          \
            FA[4*i]   = f2tf(lds32(_pa0 + i * 2048));                         \
            FA[4*i+1] = f2tf(lds32(_pa0 + i * 2048 + 1024));                  \
            FA[4*i+2] = f2tf(lds32(_pa1 + i * 2048));                         \
            FA[4*i+3] = f2tf(lds32(_pa1 + i * 2048 + 1024));                  \
        }                                                                     \
    } while (0)

#define LOAD_FB(SB, KS)                                                       \
    do {                                                                      \
        const char* _pb = (SB) + (bInv + (KS) * 4352);                        \
        _Pragma("unroll")                                                     \
        for (int j = 0; j < 8; j++){                                          \
            fb[2*j]   = f2tf(lds32(_pb + j * 32));                            \
            fb[2*j+1] = f2tf(lds32(_pb + j * 32 + 2176));                     \
        }                                                                     \
    } while (0)

#define MMA_BLOCK(FA)                                                         \
    do {                                                                      \
        _Pragma("unroll")                                                     \
        for (int i = 0; i < 4; i++)                                           \
            _Pragma("unroll")                                                 \
            for (int j = 0; j < 8; j++)                                       \
                mma_tf32(acc[i][j], FA[4*i], FA[4*i+1], FA[4*i+2], FA[4*i+3], \
                         fb[2*j], fb[2*j+1]);                                 \
    } while (0)

    // One chunk; S compile-time. fa double-buffered, fb JIT: LOAD_FB(ks+1)
    // issues right after MMA_BLOCK(ks) (fb consumed at MMA issue), and the
    // interleaved LOAD_FA covers the LDS->MMA latency for fb.
#define CHUNK_BODY(C, S)                                                      \
    do {                                                                      \
        const char* sA = dsm + (S) * A_STAGE;                                 \
        const char* sB = dsm + B_REG + (S) * B_STAGE;                         \
        LOAD_FA(fa1, sA, 1);                                                  \
        MMA_BLOCK(fa0);            /* ks0, fb holds ks0 */                    \
        LOAD_FB(sB, 1);                                                       \
        LOAD_FA(fa0, sA, 2);                                                  \
        MMA_BLOCK(fa1);            /* ks1 */                                  \
        LOAD_FB(sB, 2);                                                       \
        LOAD_FA(fa1, sA, 3);                                                  \
        MMA_BLOCK(fa0);            /* ks2 */                                  \
        LOAD_FB(sB, 3);                                                       \
        if ((C) + 3 < 32){                                                    \
            asm volatile("cp.async.wait_group 1;" ::: "memory");              \
            __syncthreads();                                                  \
            ISSUE(((C) + 3) * 32, ((S) + 3) & 3);                             \
            asm volatile("cp.async.commit_group;" ::: "memory");              \
        } else {                                                              \
            asm volatile("cp.async.wait_group 0;" ::: "memory");              \
            __syncthreads();                                                  \
        }                                                                     \
        MMA_BLOCK(fa1);            /* ks3 */                                  \
        if ((C) + 1 < 32){                                                    \
            const char* nA = dsm + (((S) + 1) & 3) * A_STAGE;                 \
            const char* nB = dsm + B_REG + (((S) + 1) & 3) * B_STAGE;         \
            LOAD_FA(fa0, nA, 0);                                              \
            LOAD_FB(nB, 0);                                                   \
        }                                                                     \
    } while (0)

    // ---- prologue: issue chunks 0..2, preload chunk 0 ks0 ----
    ISSUE(0, 0);
    asm volatile("cp.async.commit_group;" ::: "memory");
    ISSUE(32, 1);
    asm volatile("cp.async.commit_group;" ::: "memory");
    ISSUE(64, 2);
    asm volatile("cp.async.commit_group;" ::: "memory");
    asm volatile("cp.async.wait_group 1;" ::: "memory");   // stages 0,1 ready
    __syncthreads();
    LOAD_FA(fa0, dsm, 0);
    LOAD_FB(dsm + B_REG, 0);

    // ---- main loop: 32 chunks, unrolled x4 (constant stage offsets) ----
    for (int cb = 0; cb < 32; cb += 4){
        CHUNK_BODY(cb + 0, 0);
        CHUNK_BODY(cb + 1, 1);
        CHUNK_BODY(cb + 2, 2);
        CHUNK_BODY(cb + 3, 3);
    }

    // ---- epilogue: acc + bias -> y ----
    float bias0[8], bias1[8];
    #pragma unroll
    for (int j = 0; j < 8; j++){
        const int gn = n0 + wn + j * 8 + la3 * 2;
        bias0[j] = __ldg(bc + gn);
        bias1[j] = __ldg(bc + gn + 1);
    }
    #pragma unroll
    for (int i = 0; i < 4; i++){
        const int gm = m0 + wm + i * 16 + lg;
        #pragma unroll
        for (int j = 0; j < 8; j++){
            const int gn = n0 + wn + j * 8 + la3 * 2;
            float2 v0 = make_float2(acc[i][j][0] + bias0[j], acc[i][j][1] + bias1[j]);
            float2 v1 = make_float2(acc[i][j][2] + bias0[j], acc[i][j][3] + bias1[j]);
            *(float2*)(yb + (size_t)gm * ODIM + gn)       = v0;
            *(float2*)(yb + (size_t)(gm + 8) * ODIM + gn) = v1;
        }
    }
}

extern "C" void kernel_launch(void* const* d_in, const int* in_sizes, int n_in,
                              void* d_out, int out_size)
{
    const float* x       = (const float*)d_in[0];
    const int*   cat_ids = (const int*)  d_in[1];
    const float* W       = (const float*)d_in[2];
    const float* bias    = (const float*)d_in[3];
    float*       y       = (float*)d_out;

    cudaFuncSetAttribute(cslin_mma11_kernel,
                         cudaFuncAttributeMaxDynamicSharedMemorySize, SMEM_DYN);
    dim3 grid(1024 / 128, 512 / 256, 64);   // (8, 2, 64)
    cslin_mma11_kernel<<<grid, 256, SMEM_DYN>>>(x, cat_ids, W, bias, y);
}

// round 14
// speedup vs baseline: 1.9272x; 1.9272x over previous
#include <cuda_runtime.h>
#include <cuda_fp16.h>
#include <cstdint>

// CategorySpecificLinear via mma.sync.m16n8k16 FP16 (base sm_103; tcgen05 is
// rejected by this bench's ptxas target).
//
// Round 14: precision switch tf32 -> fp16 (same 10-bit mantissa, 2x tensor
// rate). Two prologue kernels pre-convert x -> fp16 and W -> fp16 TRANSPOSED
// [cat][n][k] into __device__ globals, removing all in-loop cvts and making
// every fragment a single LDS.32. Main kernel: r9 skeleton (CTA 256Mx128N,
// 8 warps 4Mx2N, warp 64x64, BK=32, 4-stage cp.async, mid-chunk barrier,
// cross-chunk preload), pitch-80B conflict-free rows.

__device__ __half g_xh[(size_t)64 * 512 * 1024];   // x as fp16 [b][t][i]
__device__ __half g_wh[(size_t)32 * 1024 * 1024];  // W as fp16 [c][n][k] (transposed)

#define A_PITCH  80
#define A_STAGE  (256 * A_PITCH)       // 20480
#define B_STAGE  (128 * A_PITCH)       // 10240
#define STG      (A_STAGE + B_STAGE)   // 30720
#define SMEM_DYN (4 * STG)             // 122880

static __device__ __forceinline__ uint32_t smem_u32(const void* p){
    uint32_t a;
    asm("{ .reg .u64 t; cvta.to.shared.u64 t, %1; cvt.u32.u64 %0, t; }" : "=r"(a) : "l"(p));
    return a;
}
static __device__ __forceinline__ void cp16(uint32_t dst, const void* src){
    asm volatile("cp.async.cg.shared.global [%0], [%1], 16;"
                 :: "r"(dst), "l"(src) : "memory");
}
static __device__ __forceinline__ void mma_f16(float d[4],
                                               uint32_t a0, uint32_t a1,
                                               uint32_t a2, uint32_t a3,
                                               uint32_t b0, uint32_t b1){
    asm volatile(
        "mma.sync.aligned.m16n8k16.row.col.f32.f16.f16.f32 "
        "{%0,%1,%2,%3}, {%4,%5,%6,%7}, {%8,%9}, {%0,%1,%2,%3};"
        : "+f"(d[0]), "+f"(d[1]), "+f"(d[2]), "+f"(d[3])
        : "r"(a0), "r"(a1), "r"(a2), "r"(a3), "r"(b0), "r"(b1));
}
static __device__ __forceinline__ uint32_t lds32(const char* p){
    return *(const uint32_t*)p;
}

// ---- prologue 1: x fp32 -> fp16 (elementwise) ----
__global__ void cvt_x_kernel(const float* __restrict__ x)
{
    const size_t N4 = (size_t)64 * 512 * 1024 / 4;
    size_t i = (size_t)blockIdx.x * blockDim.x + threadIdx.x;
    const size_t stride = (size_t)gridDim.x * blockDim.x;
    for (; i < N4; i += stride){
        float4 v = ((const float4*)x)[i];
        __half2 h0 = __floats2half2_rn(v.x, v.y);
        __half2 h1 = __floats2half2_rn(v.z, v.w);
        uint2 u;
        u.x = *(const uint32_t*)&h0;
        u.y = *(const uint32_t*)&h1;
        ((uint2*)g_xh)[i] = u;
    }
}

// ---- prologue 2: W [c][k][n] fp32 -> g_wh [c][n][k] fp16 (transpose) ----
__global__ void cvt_w_kernel(const float* __restrict__ W)
{
    __shared__ float t[32][33];
    const int c  = blockIdx.z;
    const int k0 = blockIdx.y * 32;
    const int nn0 = blockIdx.x * 32;
    const int tx = threadIdx.x & 31;
    const int ty = threadIdx.x >> 5;          // 0..7

    const float* Wp = W + (size_t)c * 1024 * 1024;
    #pragma unroll
    for (int q = 0; q < 4; q++)
        t[ty + 8 * q][tx] = Wp[(size_t)(k0 + ty + 8 * q) * 1024 + nn0 + tx];
    __syncthreads();
    __half* dst = g_wh + (size_t)c * 1024 * 1024;
    #pragma unroll
    for (int q = 0; q < 4; q++)
        dst[(size_t)(nn0 + ty + 8 * q) * 1024 + k0 + tx] =
            __float2half_rn(t[tx][ty + 8 * q]);
}

// ---- main GEMM ----
__global__ __launch_bounds__(256, 1)
void cslin_fp16_kernel(const int*   __restrict__ cat_ids,
                       const float* __restrict__ bias,
                       float*       __restrict__ y)
{
    constexpr int ODIM = 1024, KDIM = 1024, TDIM = 512;
    extern __shared__ char dsm[];

    const int tid  = threadIdx.x;
    const int wid  = tid >> 5;
    const int lane = tid & 31;
    const int la3  = lane & 3;
    const int lg   = lane >> 2;

    const int n0 = blockIdx.x * 128;
    const int m0 = blockIdx.y * 256;
    const int bb = blockIdx.z;
    const int cat = __ldg(cat_ids + bb);

    const __half* xh = g_xh + (size_t)bb  * TDIM * KDIM;
    const __half* wh = g_wh + (size_t)cat * 1024 * KDIM;
    const float*  bc = bias + (size_t)cat * ODIM;
    float*        yb = y + (size_t)bb * TDIM * ODIM;

    // ---- cp.async geometry (fp16, pitch 80B rows of 32 halves) ----
    // A: 1024 granules/chunk -> 4/thread: row m=(t>>2)+64i, q=t&3
    const __half* aSrc = xh + (size_t)(m0 + (tid >> 2)) * KDIM + ((tid & 3) << 3);
    const uint32_t aDst = smem_u32(dsm)
        + (uint32_t)((tid >> 2) * A_PITCH + ((tid & 3) << 4));
    // B: 512 granules/chunk -> 2/thread: row n=t>>1, q=(t&1), (t&1)+2
    const __half* bSrc = wh + (size_t)(n0 + (tid >> 1)) * KDIM + ((tid & 1) << 3);
    const uint32_t bDst = smem_u32(dsm) + A_STAGE
        + (uint32_t)((tid >> 1) * A_PITCH + ((tid & 1) << 4));

#define ISSUE(KC, S)                                                          \
    do {                                                                      \
        const __half* _as = aSrc + (KC);                                      \
        const uint32_t _ad = aDst + (uint32_t)((S) * STG);                    \
        _Pragma("unroll")                                                     \
        for (int i = 0; i < 4; i++)                                           \
            cp16(_ad + (uint32_t)(i * 64 * A_PITCH),                          \
                 _as + (size_t)(64 * i) * KDIM);                              \
        const __half* _bs = bSrc + (KC);                                      \
        const uint32_t _bd = bDst + (uint32_t)((S) * STG);                    \
        cp16(_bd,       _bs);                                                 \
        cp16(_bd + 32u, _bs + 16);                                            \
    } while (0)

    // ---- warp tile 64x64 ----
    const int wm = (wid & 3) * 64;
    const int wn = (wid >> 2) * 64;

    const uint32_t aInv = (uint32_t)((wm + lg) * A_PITCH + la3 * 4);
    const uint32_t bInv = (uint32_t)((wn + lg) * A_PITCH + la3 * 4);

    float acc[4][8][4];
    #pragma unroll
    for (int i = 0; i < 4; i++)
        #pragma unroll
        for (int j = 0; j < 8; j++)
            #pragma unroll
            for (int q = 0; q < 4; q++) acc[i][j][q] = 0.f;

    uint32_t fa0[16], fb0[16], fa1[16], fb1[16];

    // k-step KS covers halves [KS*16, KS*16+16): byte offset KS*32.
#define LOAD_FRAGS(FA, FB, SA, SB, KS)                                        \
    do {                                                                      \
        const char* _pb = (SB) + (bInv + (KS) * 32);                          \
        _Pragma("unroll")                                                     \
        for (int j = 0; j < 8; j++){                                          \
            FB[2*j]   = lds32(_pb + j * 8 * A_PITCH);                         \
            FB[2*j+1] = lds32(_pb + j * 8 * A_PITCH + 16);                    \
        }                                                                     \
        const char* _pa = (SA) + (aInv + (KS) * 32);                          \
        _Pragma("unroll")                                                     \
        for (int i = 0; i < 4; i++){                                          \
            FA[4*i]   = lds32(_pa + i * 16 * A_PITCH);                        \
            FA[4*i+1] = lds32(_pa + i * 16 * A_PITCH + 8 * A_PITCH);          \
            FA[4*i+2] = lds32(_pa + i * 16 * A_PITCH + 16);                   \
            FA[4*i+3] = lds32(_pa + i * 16 * A_PITCH + 8 * A_PITCH + 16);     \
        }                                                                     \
    } while (0)

#define MMA_BLOCK(FA, FB)                                                     \
    do {                                                                      \
        _Pragma("unroll")                                                     \
        for (int i = 0; i < 4; i++)                                           \
            _Pragma("unroll")                                                 \
            for (int j = 0; j < 8; j++)                                       \
                mma_f16(acc[i][j], FA[4*i], FA[4*i+1], FA[4*i+2], FA[4*i+3],  \
                        FB[2*j], FB[2*j+1]);                                  \
    } while (0)

    // chunk = BK 32 halves = 2 k-steps of K=16
#define CHUNK_BODY(C, S)                                                      \
    do {                                                                      \
        const char* sA = dsm + (S) * STG;                                     \
        const char* sB = sA + A_STAGE;                                        \
        LOAD_FRAGS(fa1, fb1, sA, sB, 1);                                      \
        MMA_BLOCK(fa0, fb0);           /* ks0 (preloaded) */                  \
        if ((C) + 3 < 32){                                                    \
            asm volatile("cp.async.wait_group 1;" ::: "memory");              \
            __syncthreads();                                                  \
            ISSUE(((C) + 3) * 32, ((S) + 3) & 3);                             \
            asm volatile("cp.async.commit_group;" ::: "memory");              \
        } else {                                                              \
            asm volatile("cp.async.wait_group 0;" ::: "memory");              \
            __syncthreads();                                                  \
        }                                                                     \
        MMA_BLOCK(fa1, fb1);           /* ks1 */                              \
        if ((C) + 1 < 32){                                                    \
            const char* nA = dsm + (((S) + 1) & 3) * STG;                     \
            const char* nB = nA + A_STAGE;                                    \
            LOAD_FRAGS(fa0, fb0, nA, nB, 0);                                  \
        }                                                                     \
    } while (0)

    // ---- prologue: issue chunks 0..2, preload chunk 0 ks0 ----
    ISSUE(0, 0);
    asm volatile("cp.async.commit_group;" ::: "memory");
    ISSUE(32, 1);
    asm volatile("cp.async.commit_group;" ::: "memory");
    ISSUE(64, 2);
    asm volatile("cp.async.commit_group;" ::: "memory");
    asm volatile("cp.async.wait_group 1;" ::: "memory");   // stages 0,1 ready
    __syncthreads();
    LOAD_FRAGS(fa0, fb0, dsm, dsm + A_STAGE, 0);

    // ---- main loop: 32 chunks, unrolled x4 ----
    for (int cb = 0; cb < 32; cb += 4){
        CHUNK_BODY(cb + 0, 0);
        CHUNK_BODY(cb + 1, 1);
        CHUNK_BODY(cb + 2, 2);
        CHUNK_BODY(cb + 3, 3);
    }

    // ---- epilogue: acc + bias -> y ----
    float bias0[8], bias1[8];
    #pragma unroll
    for (int j = 0; j < 8; j++){
        const int gn = n0 + wn + j * 8 + la3 * 2;
        bias0[j] = __ldg(bc + gn);
        bias1[j] = __ldg(bc + gn + 1);
    }
    #pragma unroll
    for (int i = 0; i < 4; i++){
        const int gm = m0 + wm + i * 16 + lg;
        #pragma unroll
        for (int j = 0; j < 8; j++){
            const int gn = n0 + wn + j * 8 + la3 * 2;
            float2 v0 = make_float2(acc[i][j][0] + bias0[j], acc[i][j][1] + bias1[j]);
            float2 v1 = make_float2(acc[i][j][2] + bias0[j], acc[i][j][3] + bias1[j]);
            *(float2*)(yb + (size_t)gm * ODIM + gn)       = v0;
            *(float2*)(yb + (size_t)(gm + 8) * ODIM + gn) = v1;
        }
    }
}

extern "C" void kernel_launch(void* const* d_in, const int* in_sizes, int n_in,
                              void* d_out, int out_size)
{
    const float* x       = (const float*)d_in[0];
    const int*   cat_ids = (const int*)  d_in[1];
    const float* W       = (const float*)d_in[2];
    const float* bias    = (const float*)d_in[3];
    float*       y       = (float*)d_out;

    // prologue conversions (graph-capturable, same stream => ordered)
    cvt_x_kernel<<<2048, 256>>>(x);
    cvt_w_kernel<<<dim3(32, 32, 32), 256>>>(W);

    cudaFuncSetAttribute(cslin_fp16_kernel,
                         cudaFuncAttributeMaxDynamicSharedMemorySize, SMEM_DYN);
    dim3 grid(1024 / 128, 512 / 256, 64);   // (8, 2, 64)
    cslin_fp16_kernel<<<grid, 256, SMEM_DYN>>>(cat_ids, bias, y);
}

// round 15
// speedup vs baseline: 2.1120x; 1.0959x over previous
#include <cuda_runtime.h>
#include <cuda_fp16.h>
#include <cstdint>

// CategorySpecificLinear via mma.sync.m16n8k16 FP16 (base sm_103; tcgen05 is
// rejected by this bench's ptxas target).
//
// Round 15: r14 + ldmatrix.x4 fragment loads. 8 LDSM per LOAD_FRAGS instead
// of 32 LDS.32 -> 4x fewer shared-load issue slots competing with HMMA.
// Pitch-80B rows are conflict-free for ldmatrix's 8-address phases.
// Prologue kernels pre-convert x -> fp16 and W -> fp16 transposed [c][n][k].

__device__ __half g_xh[(size_t)64 * 512 * 1024];   // x as fp16 [b][t][i]
__device__ __half g_wh[(size_t)32 * 1024 * 1024];  // W as fp16 [c][n][k]

#define A_PITCH  80
#define A_STAGE  (256 * A_PITCH)       // 20480
#define B_STAGE  (128 * A_PITCH)       // 10240
#define STG      (A_STAGE + B_STAGE)   // 30720
#define SMEM_DYN (4 * STG)             // 122880

static __device__ __forceinline__ uint32_t smem_u32(const void* p){
    uint32_t a;
    asm("{ .reg .u64 t; cvta.to.shared.u64 t, %1; cvt.u32.u64 %0, t; }" : "=r"(a) : "l"(p));
    return a;
}
static __device__ __forceinline__ void cp16(uint32_t dst, const void* src){
    asm volatile("cp.async.cg.shared.global [%0], [%1], 16;"
                 :: "r"(dst), "l"(src) : "memory");
}
static __device__ __forceinline__ void mma_f16(float d[4],
                                               uint32_t a0, uint32_t a1,
                                               uint32_t a2, uint32_t a3,
                                               uint32_t b0, uint32_t b1){
    asm volatile(
        "mma.sync.aligned.m16n8k16.row.col.f32.f16.f16.f32 "
        "{%0,%1,%2,%3}, {%4,%5,%6,%7}, {%8,%9}, {%0,%1,%2,%3};"
        : "+f"(d[0]), "+f"(d[1]), "+f"(d[2]), "+f"(d[3])
        : "r"(a0), "r"(a1), "r"(a2), "r"(a3), "r"(b0), "r"(b1));
}
#define LDSM4(R0, R1, R2, R3, ADDR)                                           \
    asm volatile("ldmatrix.sync.aligned.m8n8.x4.shared.b16 {%0,%1,%2,%3}, [%4];" \
                 : "=r"(R0), "=r"(R1), "=r"(R2), "=r"(R3) : "r"(ADDR))

// ---- prologue 1: x fp32 -> fp16 ----
__global__ void cvt_x_kernel(const float* __restrict__ x)
{
    const size_t N4 = (size_t)64 * 512 * 1024 / 4;
    size_t i = (size_t)blockIdx.x * blockDim.x + threadIdx.x;
    const size_t stride = (size_t)gridDim.x * blockDim.x;
    for (; i < N4; i += stride){
        float4 v = ((const float4*)x)[i];
        __half2 h0 = __floats2half2_rn(v.x, v.y);
        __half2 h1 = __floats2half2_rn(v.z, v.w);
        uint2 u;
        u.x = *(const uint32_t*)&h0;
        u.y = *(const uint32_t*)&h1;
        ((uint2*)g_xh)[i] = u;
    }
}

// ---- prologue 2: W [c][k][n] fp32 -> g_wh [c][n][k] fp16 (transpose) ----
__global__ void cvt_w_kernel(const float* __restrict__ W)
{
    __shared__ float t[32][33];
    const int c   = blockIdx.z;
    const int k0  = blockIdx.y * 32;
    const int nn0 = blockIdx.x * 32;
    const int tx  = threadIdx.x & 31;
    const int ty  = threadIdx.x >> 5;

    const float* Wp = W + (size_t)c * 1024 * 1024;
    #pragma unroll
    for (int q = 0; q < 4; q++)
        t[ty + 8 * q][tx] = Wp[(size_t)(k0 + ty + 8 * q) * 1024 + nn0 + tx];
    __syncthreads();
    __half* dst = g_wh + (size_t)c * 1024 * 1024;
    #pragma unroll
    for (int q = 0; q < 4; q++)
        dst[(size_t)(nn0 + ty + 8 * q) * 1024 + k0 + tx] =
            __float2half_rn(t[tx][ty + 8 * q]);
}

// ---- main GEMM ----
__global__ __launch_bounds__(256, 1)
void cslin_fp16b_kernel(const int*   __restrict__ cat_ids,
                        const float* __restrict__ bias,
                        float*       __restrict__ y)
{
    constexpr int ODIM = 1024, KDIM = 1024, TDIM = 512;
    extern __shared__ char dsm[];
    const uint32_t sBase = smem_u32(dsm);

    const int tid  = threadIdx.x;
    const int wid  = tid >> 5;
    const int lane = tid & 31;
    const int la3  = lane & 3;
    const int lg   = lane >> 2;

    const int n0 = blockIdx.x * 128;
    const int m0 = blockIdx.y * 256;
    const int bb = blockIdx.z;
    const int cat = __ldg(cat_ids + bb);

    const __half* xh = g_xh + (size_t)bb  * TDIM * KDIM;
    const __half* wh = g_wh + (size_t)cat * 1024 * KDIM;
    const float*  bc = bias + (size_t)cat * ODIM;
    float*        yb = y + (size_t)bb * TDIM * ODIM;

    // ---- cp.async geometry (pitch 80B rows of 32 halves) ----
    const __half* aSrc = xh + (size_t)(m0 + (tid >> 2)) * KDIM + ((tid & 3) << 3);
    const uint32_t aDst = sBase + (uint32_t)((tid >> 2) * A_PITCH + ((tid & 3) << 4));
    const __half* bSrc = wh + (size_t)(n0 + (tid >> 1)) * KDIM + ((tid & 1) << 3);
    const uint32_t bDst = sBase + A_STAGE
        + (uint32_t)((tid >> 1) * A_PITCH + ((tid & 1) << 4));

#define ISSUE(KC, S)                                                          \
    do {                                                                      \
        const __half* _as = aSrc + (KC);                                      \
        const uint32_t _ad = aDst + (uint32_t)((S) * STG);                    \
        _Pragma("unroll")                                                     \
        for (int i = 0; i < 4; i++)                                           \
            cp16(_ad + (uint32_t)(i * 64 * A_PITCH),                          \
                 _as + (size_t)(64 * i) * KDIM);                              \
        const __half* _bs = bSrc + (KC);                                      \
        const uint32_t _bd = bDst + (uint32_t)((S) * STG);                    \
        cp16(_bd,       _bs);                                                 \
        cp16(_bd + 32u, _bs + 16);                                            \
    } while (0)

    // ---- warp tile 64x64 ----
    const int wm = (wid & 3) * 64;
    const int wn = (wid >> 2) * 64;

    // ldmatrix per-lane bases (conflict-free with pitch 80B)
    // A x4: m0..m3 = (rows0-7,klo),(rows8-15,klo),(rows0-7,khi),(rows8-15,khi)
    const uint32_t aLdm = (uint32_t)((wm + (lane & 7) + ((lane >> 3) & 1) * 8) * A_PITCH
                                     + ((lane >> 4) & 1) * 16);
    // B x4: m0..m3 = (nblk j,klo),(nblk j,khi),(nblk j+1,klo),(nblk j+1,khi)
    const uint32_t bLdm = (uint32_t)(((lane & 7) + ((lane >> 4) & 1) * 8 + wn) * A_PITCH
                                     + ((lane >> 3) & 1) * 16);

    float acc[4][8][4];
    #pragma unroll
    for (int i = 0; i < 4; i++)
        #pragma unroll
        for (int j = 0; j < 8; j++)
            #pragma unroll
            for (int q = 0; q < 4; q++) acc[i][j][q] = 0.f;

    uint32_t fa0[16], fb0[16], fa1[16], fb1[16];

    // k-step KS: byte offset KS*32 within the 64B (32-half) row.
#define LOAD_FRAGS(FA, FB, SAU, SBU, KS)                                      \
    do {                                                                      \
        const uint32_t _ab = (SAU) + aLdm + (KS) * 32;                        \
        _Pragma("unroll")                                                     \
        for (int i = 0; i < 4; i++)                                           \
            LDSM4(FA[4*i], FA[4*i+1], FA[4*i+2], FA[4*i+3],                   \
                  _ab + (uint32_t)(i * 16 * A_PITCH));                        \
        const uint32_t _bb = (SBU) + bLdm + (KS) * 32;                        \
        _Pragma("unroll")                                                     \
        for (int p = 0; p < 4; p++)                                           \
            LDSM4(FB[4*p], FB[4*p+1], FB[4*p+2], FB[4*p+3],                   \
                  _bb + (uint32_t)(p * 16 * A_PITCH));                        \
    } while (0)

#define MMA_BLOCK(FA, FB)                                                     \
    do {                                                                      \
        _Pragma("unroll")                                                     \
        for (int i = 0; i < 4; i++)                                           \
            _Pragma("unroll")                                                 \
            for (int j = 0; j < 8; j++)                                       \
                mma_f16(acc[i][j], FA[4*i], FA[4*i+1], FA[4*i+2], FA[4*i+3],  \
                        FB[2*j], FB[2*j+1]);                                  \
    } while (0)

#define CHUNK_BODY(C, S)                                                      \
    do {                                                                      \
        const uint32_t sAu = sBase + (S) * STG;                               \
        const uint32_t sBu = sAu + A_STAGE;                                   \
        LOAD_FRAGS(fa1, fb1, sAu, sBu, 1);                                    \
        MMA_BLOCK(fa0, fb0);           /* ks0 (preloaded) */                  \
        if ((C) + 3 < 32){                                                    \
            asm volatile("cp.async.wait_group 1;" ::: "memory");              \
            __syncthreads();                                                  \
            ISSUE(((C) + 3) * 32, ((S) + 3) & 3);                             \
            asm volatile("cp.async.commit_group;" ::: "memory");              \
        } else {                                                              \
            asm volatile("cp.async.wait_group 0;" ::: "memory");              \
            __syncthreads();                                                  \
        }                                                                     \
        MMA_BLOCK(fa1, fb1);           /* ks1 */                              \
        if ((C) + 1 < 32){                                                    \
            const uint32_t nAu = sBase + (((S) + 1) & 3) * STG;               \
            LOAD_FRAGS(fa0, fb0, nAu, nAu + A_STAGE, 0);                      \
        }                                                                     \
    } while (0)

    // ---- prologue: issue chunks 0..2, preload chunk 0 ks0 ----
    ISSUE(0, 0);
    asm volatile("cp.async.commit_group;" ::: "memory");
    ISSUE(32, 1);
    asm volatile("cp.async.commit_group;" ::: "memory");
    ISSUE(64, 2);
    asm volatile("cp.async.commit_group;" ::: "memory");
    asm volatile("cp.async.wait_group 1;" ::: "memory");
    __syncthreads();
    LOAD_FRAGS(fa0, fb0, sBase, sBase + A_STAGE, 0);

    // ---- main loop: 32 chunks, unrolled x4 ----
    for (int cb = 0; cb < 32; cb += 4){
        CHUNK_BODY(cb + 0, 0);
        CHUNK_BODY(cb + 1, 1);
        CHUNK_BODY(cb + 2, 2);
        CHUNK_BODY(cb + 3, 3);
    }

    // ---- epilogue: acc + bias -> y ----
    float bias0[8], bias1[8];
    #pragma unroll
    for (int j = 0; j < 8; j++){
        const int gn = n0 + wn + j * 8 + la3 * 2;
        bias0[j] = __ldg(bc + gn);
        bias1[j] = __ldg(bc + gn + 1);
    }
    #pragma unroll
    for (int i = 0; i < 4; i++){
        const int gm = m0 + wm + i * 16 + lg;
        #pragma unroll
        for (int j = 0; j < 8; j++){
            const int gn = n0 + wn + j * 8 + la3 * 2;
            float2 v0 = make_float2(acc[i][j][0] + bias0[j], acc[i][j][1] + bias1[j]);
            float2 v1 = make_float2(acc[i][j][2] + bias0[j], acc[i][j][3] + bias1[j]);
            *(float2*)(yb + (size_t)gm * ODIM + gn)       = v0;
            *(float2*)(yb + (size_t)(gm + 8) * ODIM + gn) = v1;
        }
    }
}

extern "C" void kernel_launch(void* const* d_in, const int* in_sizes, int n_in,
                              void* d_out, int out_size)
{
    const float* x       = (const float*)d_in[0];
    const int*   cat_ids = (const int*)  d_in[1];
    const float* W       = (const float*)d_in[2];
    const float* bias    = (const float*)d_in[3];
    float*       y       = (float*)d_out;

    cvt_x_kernel<<<2048, 256>>>(x);
    cvt_w_kernel<<<dim3(32, 32, 32), 256>>>(W);

    cudaFuncSetAttribute(cslin_fp16b_kernel,
                         cudaFuncAttributeMaxDynamicSharedMemorySize, SMEM_DYN);
    dim3 grid(1024 / 128, 512 / 256, 64);   // (8, 2, 64)
    cslin_fp16b_kernel<<<grid, 256, SMEM_DYN>>>(cat_ids, bias, y);
}

// round 16
// speedup vs baseline: 2.2487x; 1.0647x over previous
#include <cuda_runtime.h>
#include <cuda_fp16.h>
#include <cstdint>

// CategorySpecificLinear via mma.sync.m16n8k16 FP16 (base sm_103; tcgen05 is
// rejected by this bench's ptxas target).
//
// Round 16: r15 + BK 32->64 with a 3-stage cp.async pipeline: 16 chunks
// instead of 32 -> half the barrier/wait boundaries. Pitch-144B rows stay
// conflict-free for ldmatrix (8 rows span all 32 banks) and 16B-aligned for
// cp.async. Schedule per chunk: ks0 preloaded | LD ks1, MMA ks0, LD ks2,
// MMA ks1 | barrier + ISSUE(c+2) | LD ks3, MMA ks2, MMA ks3 | preload next.

__device__ __half g_xh[(size_t)64 * 512 * 1024];   // x as fp16 [b][t][i]
__device__ __half g_wh[(size_t)32 * 1024 * 1024];  // W as fp16 [c][n][k]

#define A_PITCH  144                   // 64 halves (128B) + 16B pad
#define A_STAGE  (256 * A_PITCH)       // 36864
#define B_STAGE  (128 * A_PITCH)       // 18432
#define STG      (A_STAGE + B_STAGE)   // 55296
#define SMEM_DYN (3 * STG)             // 165888

static __device__ __forceinline__ uint32_t smem_u32(const void* p){
    uint32_t a;
    asm("{ .reg .u64 t; cvta.to.shared.u64 t, %1; cvt.u32.u64 %0, t; }" : "=r"(a) : "l"(p));
    return a;
}
static __device__ __forceinline__ void cp16(uint32_t dst, const void* src){
    asm volatile("cp.async.cg.shared.global [%0], [%1], 16;"
                 :: "r"(dst), "l"(src) : "memory");
}
static __device__ __forceinline__ void mma_f16(float d[4],
                                               uint32_t a0, uint32_t a1,
                                               uint32_t a2, uint32_t a3,
                                               uint32_t b0, uint32_t b1){
    asm volatile(
        "mma.sync.aligned.m16n8k16.row.col.f32.f16.f16.f32 "
        "{%0,%1,%2,%3}, {%4,%5,%6,%7}, {%8,%9}, {%0,%1,%2,%3};"
        : "+f"(d[0]), "+f"(d[1]), "+f"(d[2]), "+f"(d[3])
        : "r"(a0), "r"(a1), "r"(a2), "r"(a3), "r"(b0), "r"(b1));
}
#define LDSM4(R0, R1, R2, R3, ADDR)                                           \
    asm volatile("ldmatrix.sync.aligned.m8n8.x4.shared.b16 {%0,%1,%2,%3}, [%4];" \
                 : "=r"(R0), "=r"(R1), "=r"(R2), "=r"(R3) : "r"(ADDR))

// ---- prologue 1: x fp32 -> fp16 ----
__global__ void cvt_x_kernel(const float* __restrict__ x)
{
    const size_t N4 = (size_t)64 * 512 * 1024 / 4;
    size_t i = (size_t)blockIdx.x * blockDim.x + threadIdx.x;
    const size_t stride = (size_t)gridDim.x * blockDim.x;
    for (; i < N4; i += stride){
        float4 v = ((const float4*)x)[i];
        __half2 h0 = __floats2half2_rn(v.x, v.y);
        __half2 h1 = __floats2half2_rn(v.z, v.w);
        uint2 u;
        u.x = *(const uint32_t*)&h0;
        u.y = *(const uint32_t*)&h1;
        ((uint2*)g_xh)[i] = u;
    }
}

// ---- prologue 2: W [c][k][n] fp32 -> g_wh [c][n][k] fp16 (transpose) ----
__global__ void cvt_w_kernel(const float* __restrict__ W)
{
    __shared__ float t[32][33];
    const int c   = blockIdx.z;
    const int k0  = blockIdx.y * 32;
    const int nn0 = blockIdx.x * 32;
    const int tx  = threadIdx.x & 31;
    const int ty  = threadIdx.x >> 5;

    const float* Wp = W + (size_t)c * 1024 * 1024;
    #pragma unroll
    for (int q = 0; q < 4; q++)
        t[ty + 8 * q][tx] = Wp[(size_t)(k0 + ty + 8 * q) * 1024 + nn0 + tx];
    __syncthreads();
    __half* dst = g_wh + (size_t)c * 1024 * 1024;
    #pragma unroll
    for (int q = 0; q < 4; q++)
        dst[(size_t)(nn0 + ty + 8 * q) * 1024 + k0 + tx] =
            __float2half_rn(t[tx][ty + 8 * q]);
}

// ---- main GEMM ----
__global__ __launch_bounds__(256, 1)
void cslin_fp16c_kernel(const int*   __restrict__ cat_ids,
                        const float* __restrict__ bias,
                        float*       __restrict__ y)
{
    constexpr int ODIM = 1024, KDIM = 1024, TDIM = 512;
    extern __shared__ char dsm[];
    const uint32_t sBase = smem_u32(dsm);

    const int tid  = threadIdx.x;
    const int wid  = tid >> 5;
    const int lane = tid & 31;
    const int la3  = lane & 3;
    const int lg   = lane >> 2;

    const int n0 = blockIdx.x * 128;
    const int m0 = blockIdx.y * 256;
    const int bb = blockIdx.z;
    const int cat = __ldg(cat_ids + bb);

    const __half* xh = g_xh + (size_t)bb  * TDIM * KDIM;
    const __half* wh = g_wh + (size_t)cat * 1024 * KDIM;
    const float*  bc = bias + (size_t)cat * ODIM;
    float*        yb = y + (size_t)bb * TDIM * ODIM;

    // ---- cp.async geometry: chunk = 64 halves (128B) per row ----
    // A: 2048 granules -> 8/thread: rows (t>>3)+32i, granule t&7
    const __half* aSrc = xh + (size_t)(m0 + (tid >> 3)) * KDIM + ((tid & 7) << 3);
    const uint32_t aDst = sBase + (uint32_t)((tid >> 3) * A_PITCH + ((tid & 7) << 4));
    // B: 1024 granules -> 4/thread: row t>>1, granules (t&1)*4 + j
    const __half* bSrc = wh + (size_t)(n0 + (tid >> 1)) * KDIM + ((tid & 1) << 5);
    const uint32_t bDst = sBase + A_STAGE
        + (uint32_t)((tid >> 1) * A_PITCH + ((tid & 1) << 6));

#define ISSUE(KC, S)                                                          \
    do {                                                                      \
        const __half* _as = aSrc + (KC);                                      \
        const uint32_t _ad = aDst + (uint32_t)((S) * STG);                    \
        _Pragma("unroll")                                                     \
        for (int i = 0; i < 8; i++)                                           \
            cp16(_ad + (uint32_t)(i * 32 * A_PITCH),                          \
                 _as + (size_t)(32 * i) * KDIM);                              \
        const __half* _bs = bSrc + (KC);                                      \
        const uint32_t _bd = bDst + (uint32_t)((S) * STG);                    \
        _Pragma("unroll")                                                     \
        for (int j = 0; j < 4; j++)                                           \
            cp16(_bd + (uint32_t)(j * 16), _bs + j * 8);                      \
    } while (0)

    // ---- warp tile 64x64 ----
    const int wm = (wid & 3) * 64;
    const int wn = (wid >> 2) * 64;

    const uint32_t aLdm = (uint32_t)((wm + (lane & 7) + ((lane >> 3) & 1) * 8) * A_PITCH
                                     + ((lane >> 4) & 1) * 16);
    const uint32_t bLdm = (uint32_t)(((lane & 7) + ((lane >> 4) & 1) * 8 + wn) * A_PITCH
                                     + ((lane >> 3) & 1) * 16);

    float acc[4][8][4];
    #pragma unroll
    for (int i = 0; i < 4; i++)
        #pragma unroll
        for (int j = 0; j < 8; j++)
            #pragma unroll
            for (int q = 0; q < 4; q++) acc[i][j][q] = 0.f;

    uint32_t fa0[16], fb0[16], fa1[16], fb1[16];

    // k-step KS (0..3): byte offset KS*32 within the 128B row.
#define LOAD_FRAGS(FA, FB, SAU, SBU, KS)                                      \
    do {                                                                      \
        const uint32_t _ab = (SAU) + aLdm + (KS) * 32;                        \
        _Pragma("unroll")                                                     \
        for (int i = 0; i < 4; i++)                                           \
            LDSM4(FA[4*i], FA[4*i+1], FA[4*i+2], FA[4*i+3],                   \
                  _ab + (uint32_t)(i * 16 * A_PITCH));                        \
        const uint32_t _bb = (SBU) + bLdm + (KS) * 32;                        \
        _Pragma("unroll")                                                     \
        for (int p = 0; p < 4; p++)                                           \
            LDSM4(FB[4*p], FB[4*p+1], FB[4*p+2], FB[4*p+3],                   \
                  _bb + (uint32_t)(p * 16 * A_PITCH));                        \
    } while (0)

#define MMA_BLOCK(FA, FB)                                                     \
    do {                                                                      \
        _Pragma("unroll")                                                     \
        for (int i = 0; i < 4; i++)                                           \
            _Pragma("unroll")                                                 \
            for (int j = 0; j < 8; j++)                                       \
                mma_f16(acc[i][j], FA[4*i], FA[4*i+1], FA[4*i+2], FA[4*i+3],  \
                        FB[2*j], FB[2*j+1]);                                  \
    } while (0)

    // Chunk c uses stage S=c%3. Mid-chunk barrier protects the overwrite of
    // stage (c+2)%3 == (c-1)%3 (its readers all finished in chunk c-1).
    // wait_group 1 before the cross-chunk preload guarantees chunk c+1 is
    // resident (only the newest group, chunk c+2, may still be pending).
#define CHUNK_BODY(C, S)                                                      \
    do {                                                                      \
        const uint32_t sAu = sBase + (S) * STG;                               \
        const uint32_t sBu = sAu + A_STAGE;                                   \
        LOAD_FRAGS(fa1, fb1, sAu, sBu, 1);                                    \
        MMA_BLOCK(fa0, fb0);           /* ks0 (preloaded) */                  \
        LOAD_FRAGS(fa0, fb0, sAu, sBu, 2);                                    \
        MMA_BLOCK(fa1, fb1);           /* ks1 */                              \
        if ((C) + 2 < 16){                                                    \
            __syncthreads();                                                  \
            ISSUE(((C) + 2) * 64, ((S) + 2) % 3);                             \
            asm volatile("cp.async.commit_group;" ::: "memory");              \
        }                                                                     \
        LOAD_FRAGS(fa1, fb1, sAu, sBu, 3);                                    \
        MMA_BLOCK(fa0, fb0);           /* ks2 */                              \
        MMA_BLOCK(fa1, fb1);           /* ks3 */                              \
        if ((C) + 1 < 16){                                                    \
            asm volatile("cp.async.wait_group 1;" ::: "memory");              \
            __syncthreads();                                                  \
            const uint32_t nAu = sBase + (((S) + 1) % 3) * STG;               \
            LOAD_FRAGS(fa0, fb0, nAu, nAu + A_STAGE, 0);                      \
        }                                                                     \
    } while (0)

    // ---- prologue: issue chunks 0,1; preload chunk 0 ks0 ----
    ISSUE(0, 0);
    asm volatile("cp.async.commit_group;" ::: "memory");
    ISSUE(64, 1);
    asm volatile("cp.async.commit_group;" ::: "memory");
    asm volatile("cp.async.wait_group 1;" ::: "memory");   // chunk 0 ready
    __syncthreads();
    LOAD_FRAGS(fa0, fb0, sBase, sBase + A_STAGE, 0);

    // ---- main loop: 16 chunks of BK=64, unrolled x3 + tail ----
    CHUNK_BODY(0, 0);   CHUNK_BODY(1, 1);   CHUNK_BODY(2, 2);
    CHUNK_BODY(3, 0);   CHUNK_BODY(4, 1);   CHUNK_BODY(5, 2);
    CHUNK_BODY(6, 0);   CHUNK_BODY(7, 1);   CHUNK_BODY(8, 2);
    CHUNK_BODY(9, 0);   CHUNK_BODY(10, 1);  CHUNK_BODY(11, 2);
    CHUNK_BODY(12, 0);  CHUNK_BODY(13, 1);  CHUNK_BODY(14, 2);
    CHUNK_BODY(15, 0);

    // ---- epilogue: acc + bias -> y ----
    float bias0[8], bias1[8];
    #pragma unroll
    for (int j = 0; j < 8; j++){
        const int gn = n0 + wn + j * 8 + la3 * 2;
        bias0[j] = __ldg(bc + gn);
        bias1[j] = __ldg(bc + gn + 1);
    }
    #pragma unroll
    for (int i = 0; i < 4; i++){
        const int gm = m0 + wm + i * 16 + lg;
        #pragma unroll
        for (int j = 0; j < 8; j++){
            const int gn = n0 + wn + j * 8 + la3 * 2;
            float2 v0 = make_float2(acc[i][j][0] + bias0[j], acc[i][j][1] + bias1[j]);
            float2 v1 = make_float2(acc[i][j][2] + bias0[j], acc[i][j][3] + bias1[j]);
            *(float2*)(yb + (size_t)gm * ODIM + gn)       = v0;
            *(float2*)(yb + (size_t)(gm + 8) * ODIM + gn) = v1;
        }
    }
}

extern "C" void kernel_launch(void* const* d_in, const int* in_sizes, int n_in,
                              void* d_out, int out_size)
{
    const float* x       = (const float*)d_in[0];
    const int*   cat_ids = (const int*)  d_in[1];
    const float* W       = (const float*)d_in[2];
    const float* bias    = (const float*)d_in[3];
    float*       y       = (float*)d_out;

    cvt_x_kernel<<<2048, 256>>>(x);
    cvt_w_kernel<<<dim3(32, 32, 32), 256>>>(W);

    cudaFuncSetAttribute(cslin_fp16c_kernel,
                         cudaFuncAttributeMaxDynamicSharedMemorySize, SMEM_DYN);
    dim3 grid(1024 / 128, 512 / 256, 64);   // (8, 2, 64)
    cslin_fp16c_kernel<<<grid, 256, SMEM_DYN>>>(cat_ids, bias, y);
}

// round 17
// speedup vs baseline: 2.3103x; 1.0274x over previous
#include <cuda_runtime.h>
#include <cuda_fp16.h>
#include <cstdint>

// CategorySpecificLinear via mma.sync.m16n8k16 FP16 (base sm_103; tcgen05 is
// rejected by this bench's ptxas target).
//
// Round 17: r16 + (1) single barrier per chunk (mid-chunk ISSUE needs no
// barrier: the previous chunk's end barrier already separates the stage's
// last readers from the overwrite) and (2) W kept in [c][k][n] layout with
// ldmatrix.x4.trans for B fragments -> cvt_w becomes a pure streaming
// elementwise convert (no SMEM transpose).

__device__ __half g_xh[(size_t)64 * 512 * 1024];   // x as fp16 [b][t][i]
__device__ __half g_wh[(size_t)32 * 1024 * 1024];  // W as fp16 [c][k][n]

#define A_PITCH  144                   // 64 halves (128B) + 16B pad
#define A_STAGE  (256 * A_PITCH)       // 36864
#define B_PITCH  272                   // 128 halves (256B) + 16B pad
#define B_STAGE  (64 * B_PITCH)        // 17408
#define STG      (A_STAGE + B_STAGE)   // 54272
#define SMEM_DYN (3 * STG)             // 162816

static __device__ __forceinline__ uint32_t smem_u32(const void* p){
    uint32_t a;
    asm("{ .reg .u64 t; cvta.to.shared.u64 t, %1; cvt.u32.u64 %0, t; }" : "=r"(a) : "l"(p));
    return a;
}
static __device__ __forceinline__ void cp16(uint32_t dst, const void* src){
    asm volatile("cp.async.cg.shared.global [%0], [%1], 16;"
                 :: "r"(dst), "l"(src) : "memory");
}
static __device__ __forceinline__ void mma_f16(float d[4],
                                               uint32_t a0, uint32_t a1,
                                               uint32_t a2, uint32_t a3,
                                               uint32_t b0, uint32_t b1){
    asm volatile(
        "mma.sync.aligned.m16n8k16.row.col.f32.f16.f16.f32 "
        "{%0,%1,%2,%3}, {%4,%5,%6,%7}, {%8,%9}, {%0,%1,%2,%3};"
        : "+f"(d[0]), "+f"(d[1]), "+f"(d[2]), "+f"(d[3])
        : "r"(a0), "r"(a1), "r"(a2), "r"(a3), "r"(b0), "r"(b1));
}
#define LDSM4(R0, R1, R2, R3, ADDR)                                           \
    asm volatile("ldmatrix.sync.aligned.m8n8.x4.shared.b16 {%0,%1,%2,%3}, [%4];" \
                 : "=r"(R0), "=r"(R1), "=r"(R2), "=r"(R3) : "r"(ADDR))
#define LDSM4T(R0, R1, R2, R3, ADDR)                                          \
    asm volatile("ldmatrix.sync.aligned.m8n8.x4.trans.shared.b16 {%0,%1,%2,%3}, [%4];" \
                 : "=r"(R0), "=r"(R1), "=r"(R2), "=r"(R3) : "r"(ADDR))

// ---- prologue: fp32 -> fp16 elementwise (used for both x and W) ----
__global__ void cvt_kernel(const float* __restrict__ src,
                           __half* __restrict__ dst, size_t n4)
{
    size_t i = (size_t)blockIdx.x * blockDim.x + threadIdx.x;
    const size_t stride = (size_t)gridDim.x * blockDim.x;
    for (; i < n4; i += stride){
        float4 v = ((const float4*)src)[i];
        __half2 h0 = __floats2half2_rn(v.x, v.y);
        __half2 h1 = __floats2half2_rn(v.z, v.w);
        uint2 u;
        u.x = *(const uint32_t*)&h0;
        u.y = *(const uint32_t*)&h1;
        ((uint2*)dst)[i] = u;
    }
}

// ---- main GEMM ----
__global__ __launch_bounds__(256, 1)
void cslin_fp16d_kernel(const int*   __restrict__ cat_ids,
                        const float* __restrict__ bias,
                        float*       __restrict__ y)
{
    constexpr int ODIM = 1024, KDIM = 1024, TDIM = 512;
    extern __shared__ char dsm[];
    const uint32_t sBase = smem_u32(dsm);

    const int tid  = threadIdx.x;
    const int wid  = tid >> 5;
    const int lane = tid & 31;
    const int la3  = lane & 3;
    const int lg   = lane >> 2;

    const int n0 = blockIdx.x * 128;
    const int m0 = blockIdx.y * 256;
    const int bb = blockIdx.z;
    const int cat = __ldg(cat_ids + bb);

    const __half* xh = g_xh + (size_t)bb  * TDIM * KDIM;
    const __half* wh = g_wh + (size_t)cat * 1024 * KDIM;   // [k][n]
    const float*  bc = bias + (size_t)cat * ODIM;
    float*        yb = y + (size_t)bb * TDIM * ODIM;

    // ---- cp.async geometry ----
    // A chunk 256m x 64k: 2048 granules -> 8/thread: rows (t>>3)+32i, gran t&7
    const __half* aSrc = xh + (size_t)(m0 + (tid >> 3)) * KDIM + ((tid & 7) << 3);
    const uint32_t aDst = sBase + (uint32_t)((tid >> 3) * A_PITCH + ((tid & 7) << 4));
    // B chunk 64k x 128n ([k][n]): 1024 granules -> 4/thread:
    // row k = t>>2, granules (t&3)*4 + i
    const __half* bSrc = wh + (size_t)(tid >> 2) * ODIM + n0 + ((tid & 3) << 5);
    const uint32_t bDst = sBase + A_STAGE
        + (uint32_t)((tid >> 2) * B_PITCH + ((tid & 3) << 6));

#define ISSUE(KC, S)                                                          \
    do {                                                                      \
        const __half* _as = aSrc + (KC);                                      \
        const uint32_t _ad = aDst + (uint32_t)((S) * STG);                    \
        _Pragma("unroll")                                                     \
        for (int i = 0; i < 8; i++)                                           \
            cp16(_ad + (uint32_t)(i * 32 * A_PITCH),                          \
                 _as + (size_t)(32 * i) * KDIM);                              \
        const __half* _bs = bSrc + (size_t)(KC) * ODIM;                       \
        const uint32_t _bd = bDst + (uint32_t)((S) * STG);                    \
        _Pragma("unroll")                                                     \
        for (int i = 0; i < 4; i++)                                           \
            cp16(_bd + (uint32_t)(i * 16), _bs + i * 8);                      \
    } while (0)

    // ---- warp tile 64x64 ----
    const int wm = (wid & 3) * 64;
    const int wn = (wid >> 2) * 64;

    const uint32_t aLdm = (uint32_t)((wm + (lane & 7) + ((lane >> 3) & 1) * 8) * A_PITCH
                                     + ((lane >> 4) & 1) * 16);
    // B trans: lane -> k_local = (lane&7) + ((lane>>3)&1)*8, n = wn + ((lane>>4)&1)*8
    const uint32_t bLdm = (uint32_t)(A_STAGE
        + ((lane & 7) + ((lane >> 3) & 1) * 8) * B_PITCH
        + (wn + ((lane >> 4) & 1) * 8) * 2);

    float acc[4][8][4];
    #pragma unroll
    for (int i = 0; i < 4; i++)
        #pragma unroll
        for (int j = 0; j < 8; j++)
            #pragma unroll
            for (int q = 0; q < 4; q++) acc[i][j][q] = 0.f;

    uint32_t fa0[16], fb0[16], fa1[16], fb1[16];

    // k-step KS (0..3): A byte offset KS*32 in row; B: KS*16 k-rows.
#define LOAD_FRAGS(FA, FB, SU, KS)                                            \
    do {                                                                      \
        const uint32_t _ab = (SU) + aLdm + (KS) * 32;                         \
        _Pragma("unroll")                                                     \
        for (int i = 0; i < 4; i++)                                           \
            LDSM4(FA[4*i], FA[4*i+1], FA[4*i+2], FA[4*i+3],                   \
                  _ab + (uint32_t)(i * 16 * A_PITCH));                        \
        const uint32_t _bb = (SU) + bLdm + (KS) * (16 * B_PITCH);             \
        _Pragma("unroll")                                                     \
        for (int p = 0; p < 4; p++)                                           \
            LDSM4T(FB[4*p], FB[4*p+1], FB[4*p+2], FB[4*p+3],                  \
                   _bb + (uint32_t)(p * 32));                                 \
    } while (0)

#define MMA_BLOCK(FA, FB)                                                     \
    do {                                                                      \
        _Pragma("unroll")                                                     \
        for (int i = 0; i < 4; i++)                                           \
            _Pragma("unroll")                                                 \
            for (int j = 0; j < 8; j++)                                       \
                mma_f16(acc[i][j], FA[4*i], FA[4*i+1], FA[4*i+2], FA[4*i+3],  \
                        FB[2*j], FB[2*j+1]);                                  \
    } while (0)

    // Single barrier per chunk. Mid-chunk ISSUE(c+2) overwrites stage
    // (c+2)%3 == (c-1)%3 whose readers all finished before the END barrier
    // of chunk c-1 -> no extra barrier needed. End of chunk: wait_group 1
    // (chunk c+1 resident; only c+2 may be pending), barrier (cross-thread
    // visibility of c+1's cp.async + protects next chunk's overwrite),
    // then preload chunk c+1 ks0 fragments.
#define CHUNK_BODY(C, S)                                                      \
    do {                                                                      \
        const uint32_t sU = sBase + (S) * STG;                                \
        LOAD_FRAGS(fa1, fb1, sU, 1);                                          \
        MMA_BLOCK(fa0, fb0);           /* ks0 (preloaded) */                  \
        LOAD_FRAGS(fa0, fb0, sU, 2);                                          \
        MMA_BLOCK(fa1, fb1);           /* ks1 */                              \
        if ((C) + 2 < 16){                                                    \
            ISSUE(((C) + 2) * 64, ((S) + 2) % 3);                             \
            asm volatile("cp.async.commit_group;" ::: "memory");              \
        }                                                                     \
        LOAD_FRAGS(fa1, fb1, sU, 3);                                          \
        MMA_BLOCK(fa0, fb0);           /* ks2 */                              \
        MMA_BLOCK(fa1, fb1);           /* ks3 */                              \
        if ((C) + 1 < 16){                                                    \
            asm volatile("cp.async.wait_group 1;" ::: "memory");              \
            __syncthreads();                                                  \
            const uint32_t nU = sBase + (((S) + 1) % 3) * STG;                \
            LOAD_FRAGS(fa0, fb0, nU, 0);                                      \
        }                                                                     \
    } while (0)

    // ---- prologue: issue chunks 0,1; preload chunk 0 ks0 ----
    ISSUE(0, 0);
    asm volatile("cp.async.commit_group;" ::: "memory");
    ISSUE(64, 1);
    asm volatile("cp.async.commit_group;" ::: "memory");
    asm volatile("cp.async.wait_group 1;" ::: "memory");   // chunk 0 ready
    __syncthreads();
    LOAD_FRAGS(fa0, fb0, sBase, 0);

    // ---- main loop: 16 chunks of BK=64 ----
    CHUNK_BODY(0, 0);   CHUNK_BODY(1, 1);   CHUNK_BODY(2, 2);
    CHUNK_BODY(3, 0);   CHUNK_BODY(4, 1);   CHUNK_BODY(5, 2);
    CHUNK_BODY(6, 0);   CHUNK_BODY(7, 1);   CHUNK_BODY(8, 2);
    CHUNK_BODY(9, 0);   CHUNK_BODY(10, 1);  CHUNK_BODY(11, 2);
    CHUNK_BODY(12, 0);  CHUNK_BODY(13, 1);  CHUNK_BODY(14, 2);
    CHUNK_BODY(15, 0);

    // ---- epilogue: acc + bias -> y ----
    float bias0[8], bias1[8];
    #pragma unroll
    for (int j = 0; j < 8; j++){
        const int gn = n0 + wn + j * 8 + la3 * 2;
        bias0[j] = __ldg(bc + gn);
        bias1[j] = __ldg(bc + gn + 1);
    }
    #pragma unroll
    for (int i = 0; i < 4; i++){
        const int gm = m0 + wm + i * 16 + lg;
        #pragma unroll
        for (int j = 0; j < 8; j++){
            const int gn = n0 + wn + j * 8 + la3 * 2;
            float2 v0 = make_float2(acc[i][j][0] + bias0[j], acc[i][j][1] + bias1[j]);
            float2 v1 = make_float2(acc[i][j][2] + bias0[j], acc[i][j][3] + bias1[j]);
            *(float2*)(yb + (size_t)gm * ODIM + gn)       = v0;
            *(float2*)(yb + (size_t)(gm + 8) * ODIM + gn) = v1;
        }
    }
}

extern "C" void kernel_launch(void* const* d_in, const int* in_sizes, int n_in,
                              void* d_out, int out_size)
{
    const float* x       = (const float*)d_in[0];
    const int*   cat_ids = (const int*)  d_in[1];
    const float* W       = (const float*)d_in[2];
    const float* bias    = (const float*)d_in[3];
    float*       y       = (float*)d_out;

    __half* d_xh = nullptr; __half* d_wh = nullptr;
    cudaGetSymbolAddress((void**)&d_xh, g_xh);
    cudaGetSymbolAddress((void**)&d_wh, g_wh);

    cvt_kernel<<<2048, 256>>>(x, d_xh, (size_t)64 * 512 * 1024 / 4);
    cvt_kernel<<<2048, 256>>>(W, d_wh, (size_t)32 * 1024 * 1024 / 4);

    cudaFuncSetAttribute(cslin_fp16d_kernel,
                         cudaFuncAttributeMaxDynamicSharedMemorySize, SMEM_DYN);
    dim3 grid(1024 / 128, 512 / 256, 64);   // (8, 2, 64)
    cslin_fp16d_kernel<<<grid, 256, SMEM_DYN>>>(cat_ids, bias, y);
}